// round 1
// baseline (speedup 1.0000x reference)
#include <cuda_runtime.h>
#include <cuda_bf16.h>
#include <math.h>

// Problem constants
#define B_   16
#define L_   128
#define KW   8            // window K
#define NPAIR 2104        // number of pairs |j-i|<=8
#define GCN  512
#define PE   64
#define PF   1088         // PAIR_FEAT
#define M_   2048         // B*L rows
#define NREL 17           // 2K+1

// ---------------- scratch (device globals; no cudaMalloc allowed) -------------
__device__ float g_Aemo[M_ * PF];       // 8.9 MB
__device__ float g_Acau[M_ * PF];       // 8.9 MB
__device__ float g_Apos[NREL * PF];     // includes b1
__device__ float g_f[NREL * PE];        // smoothed table (17 x 64)
__device__ int   g_pi[NPAIR];
__device__ int   g_pj[NPAIR];
__device__ int   g_pr[NPAIR];           // rel + K  (0..16)

// ---------------- init: pair indices (+ optional emo_cau_pos tail) -----------
__global__ void init_pairs_kernel(float* __restrict__ out, int out_size) {
    int i = threadIdx.x;           // 0..127, one thread per utterance i
    if (i >= L_) return;
    // offset = number of pairs before row i
    int off = 0;
    for (int t = 0; t < i; t++) {
        int lo = t - KW; if (lo < 0) lo = 0;
        int hi = t + KW; if (hi > L_ - 1) hi = L_ - 1;
        off += hi - lo + 1;
    }
    int lo = i - KW; if (lo < 0) lo = 0;
    int hi = i + KW; if (hi > L_ - 1) hi = L_ - 1;
    bool write_pos = (out_size == B_ * NPAIR + 2 * NPAIR);
    for (int j = lo; j <= hi; j++) {
        int p = off + (j - lo);
        g_pi[p] = i;
        g_pj[p] = j;
        g_pr[p] = (j - i) + KW;
        if (write_pos) {
            out[B_ * NPAIR + 2 * p + 0] = (float)(i + 1);
            out[B_ * NPAIR + 2 * p + 1] = (float)(j + 1);
        }
    }
}

// ---------------- init: smoothed positional table f [17 x 64] ---------------
// f[r][e] = sum_{d=0..16} (L - |d-K|) * exp(-(r-d)^2) * pos_emb[d][e]
__global__ void init_f_kernel(const float* __restrict__ pos_emb) {
    int idx = blockIdx.x * blockDim.x + threadIdx.x;
    if (idx >= NREL * PE) return;
    int r = idx / PE;
    int e = idx % PE;
    float s = 0.f;
    #pragma unroll
    for (int d = 0; d < NREL; d++) {
        int ad = d - KW; if (ad < 0) ad = -ad;
        float cnt = (float)(L_ - ad);
        int dd = r - d;
        float w = cnt * expf(-(float)(dd * dd));
        s += w * pos_emb[d * PE + e];
    }
    g_f[idx] = s;
}

// ---------------- init: A_pos[r][g] = b1[g] + sum_e f[r][e]*W1[g][1024+e] ----
__global__ void init_apos_kernel(const float* __restrict__ W1,
                                 const float* __restrict__ b1) {
    int idx = blockIdx.x * blockDim.x + threadIdx.x;
    if (idx >= NREL * PF) return;
    int r = idx / PF;
    int g = idx % PF;
    float s = b1[g];
    const float* w = W1 + g * PF + 2 * GCN;   // columns 1024..1087
    const float* f = g_f + r * PE;
    #pragma unroll 8
    for (int e = 0; e < PE; e++) s += f[e] * w[e];
    g_Apos[idx] = s;
}

// ---------------- GEMM: C[m,g] = sum_k X[m,k] * W1[g, koff+k], K=512 --------
// X: [2048, 512] row-major. W1: [1088,1088] row-major. C: [2048,1088].
// z=0: X=h_emo, koff=0, C=g_Aemo ; z=1: X=h_cause, koff=512, C=g_Acau
#define BM 128
#define BN 64
#define BKK 16
#define ASTR (BM + 4)
#define BSTR (BN + 4)

__global__ void __launch_bounds__(256, 2)
gemm_kernel(const float* __restrict__ Xemo, const float* __restrict__ Xcau,
            const float* __restrict__ W1) {
    __shared__ __align__(16) float As[BKK][ASTR];
    __shared__ __align__(16) float Bs[BKK][BSTR];

    const int z = blockIdx.z;
    const float* __restrict__ X = z ? Xcau : Xemo;
    float* __restrict__ C = z ? g_Acau : g_Aemo;
    const int koff = z * GCN;

    const int tid = threadIdx.x;
    const int m0 = blockIdx.y * BM;
    const int n0 = blockIdx.x * BN;
    const int ty = tid >> 4;   // 0..15 -> rows (x8)
    const int tx = tid & 15;   // 0..15 -> cols (x4)

    float acc[8][4];
    #pragma unroll
    for (int a = 0; a < 8; a++)
        #pragma unroll
        for (int b = 0; b < 4; b++) acc[a][b] = 0.f;

    for (int k0 = 0; k0 < GCN; k0 += BKK) {
        // A tile: 128x16 = 512 float4, 2 per thread (transposed into smem)
        #pragma unroll
        for (int l = 0; l < 2; l++) {
            int q = tid + l * 256;
            int row = q >> 2;
            int kc = (q & 3) * 4;
            float4 v = *(const float4*)(X + (m0 + row) * GCN + k0 + kc);
            As[kc + 0][row] = v.x;
            As[kc + 1][row] = v.y;
            As[kc + 2][row] = v.z;
            As[kc + 3][row] = v.w;
        }
        // B tile: 64x16 = 256 float4, 1 per thread
        {
            int g = tid >> 2;
            int kc = (tid & 3) * 4;
            float4 v = *(const float4*)(W1 + (n0 + g) * PF + koff + k0 + kc);
            Bs[kc + 0][g] = v.x;
            Bs[kc + 1][g] = v.y;
            Bs[kc + 2][g] = v.z;
            Bs[kc + 3][g] = v.w;
        }
        __syncthreads();

        #pragma unroll
        for (int k = 0; k < BKK; k++) {
            float4 a0 = *(const float4*)&As[k][ty * 8];
            float4 a1 = *(const float4*)&As[k][ty * 8 + 4];
            float4 bv = *(const float4*)&Bs[k][tx * 4];
            float ar[8] = {a0.x, a0.y, a0.z, a0.w, a1.x, a1.y, a1.z, a1.w};
            float br[4] = {bv.x, bv.y, bv.z, bv.w};
            #pragma unroll
            for (int mm = 0; mm < 8; mm++)
                #pragma unroll
                for (int nn = 0; nn < 4; nn++)
                    acc[mm][nn] = fmaf(ar[mm], br[nn], acc[mm][nn]);
        }
        __syncthreads();
    }

    #pragma unroll
    for (int mm = 0; mm < 8; mm++) {
        float4 v = make_float4(acc[mm][0], acc[mm][1], acc[mm][2], acc[mm][3]);
        *(float4*)(C + (m0 + ty * 8 + mm) * PF + n0 + tx * 4) = v;
    }
}

// ---------------- epilogue: pred[b,p] = W2 . relu(Ae + Ac + Apos) + b2 -------
__global__ void __launch_bounds__(256)
epilogue_kernel(const float* __restrict__ W2, const float* __restrict__ b2,
                float* __restrict__ out) {
    int gw = (blockIdx.x * blockDim.x + threadIdx.x) >> 5;  // global warp id
    int lane = threadIdx.x & 31;
    if (gw >= B_ * NPAIR) return;
    int b = gw / NPAIR;
    int p = gw - b * NPAIR;

    int i = g_pi[p];
    int j = g_pj[p];
    int r = g_pr[p];

    const float4* ae = (const float4*)(g_Aemo + (b * L_ + i) * PF);
    const float4* ac = (const float4*)(g_Acau + (b * L_ + j) * PF);
    const float4* ap = (const float4*)(g_Apos + r * PF);
    const float4* w2 = (const float4*)W2;

    float sum = 0.f;
    #pragma unroll
    for (int t = 0; t < 9; t++) {
        int c4 = t * 32 + lane;
        if (c4 < PF / 4) {
            float4 e = ae[c4];
            float4 c = ac[c4];
            float4 q = ap[c4];
            float4 w = w2[c4];
            float v0 = fmaxf(e.x + c.x + q.x, 0.f);
            float v1 = fmaxf(e.y + c.y + q.y, 0.f);
            float v2 = fmaxf(e.z + c.z + q.z, 0.f);
            float v3 = fmaxf(e.w + c.w + q.w, 0.f);
            sum = fmaf(v0, w.x, sum);
            sum = fmaf(v1, w.y, sum);
            sum = fmaf(v2, w.z, sum);
            sum = fmaf(v3, w.w, sum);
        }
    }
    // warp reduce
    #pragma unroll
    for (int o = 16; o > 0; o >>= 1)
        sum += __shfl_xor_sync(0xFFFFFFFF, sum, o);

    if (lane == 0) out[b * NPAIR + p] = sum + b2[0];
}

// ---------------- launch ------------------------------------------------------
extern "C" void kernel_launch(void* const* d_in, const int* in_sizes, int n_in,
                              void* d_out, int out_size) {
    const float* h_emo  = (const float*)d_in[0];
    const float* h_cau  = (const float*)d_in[1];
    const float* pos    = (const float*)d_in[2];
    const float* W1     = (const float*)d_in[3];
    const float* b1     = (const float*)d_in[4];
    const float* W2     = (const float*)d_in[5];
    const float* b2     = (const float*)d_in[6];
    float* out = (float*)d_out;

    init_pairs_kernel<<<1, 128>>>(out, out_size);
    init_f_kernel<<<(NREL * PE + 255) / 256, 256>>>(pos);
    init_apos_kernel<<<(NREL * PF + 255) / 256, 256>>>(W1, b1);

    dim3 ggrid(PF / BN, M_ / BM, 2);   // (17, 16, 2)
    gemm_kernel<<<ggrid, 256>>>(h_emo, h_cau, W1);

    int warps = B_ * NPAIR;
    int blocks = (warps * 32 + 255) / 256;
    epilogue_kernel<<<blocks, 256>>>(W2, b2, out);
}

// round 2
// speedup vs baseline: 1.3058x; 1.3058x over previous
#include <cuda_runtime.h>
#include <cuda_bf16.h>
#include <math.h>

// Problem constants
#define B_   16
#define L_   128
#define KW   8            // window K
#define NPAIR 2104
#define GCN  512
#define PE   64
#define PF   1088         // PAIR_FEAT
#define M_   2048         // B*L rows
#define NREL 17           // 2K+1
#define KP   1536         // split-3 K' = 3*GCN

// ---------------- scratch ----------------------------------------------------
__device__ float g_Aemo[M_ * PF];       // 8.9 MB
__device__ float g_Acau[M_ * PF];       // 8.9 MB
__device__ float g_Apos[NREL * PF];
__device__ float g_f[NREL * PE];
__device__ int   g_pi[NPAIR];
__device__ int   g_pj[NPAIR];
__device__ int   g_pr[NPAIR];
__device__ __nv_bfloat16 g_Ae[M_ * KP];   // A' emo  [hi|hi|lo]
__device__ __nv_bfloat16 g_Ac[M_ * KP];   // A' cau
__device__ __nv_bfloat16 g_Be[PF * KP];   // B' emo  [hi|lo|hi]  (row = out feature g)
__device__ __nv_bfloat16 g_Bc[PF * KP];   // B' cau

// ---------------- init: pair indices -----------------------------------------
__global__ void init_pairs_kernel(float* __restrict__ out, int out_size) {
    int i = threadIdx.x;
    if (i >= L_) return;
    int off = 0;
    for (int t = 0; t < i; t++) {
        int lo = t - KW; if (lo < 0) lo = 0;
        int hi = t + KW; if (hi > L_ - 1) hi = L_ - 1;
        off += hi - lo + 1;
    }
    int lo = i - KW; if (lo < 0) lo = 0;
    int hi = i + KW; if (hi > L_ - 1) hi = L_ - 1;
    bool write_pos = (out_size == B_ * NPAIR + 2 * NPAIR);
    for (int j = lo; j <= hi; j++) {
        int p = off + (j - lo);
        g_pi[p] = i;
        g_pj[p] = j;
        g_pr[p] = (j - i) + KW;
        if (write_pos) {
            out[B_ * NPAIR + 2 * p + 0] = (float)(i + 1);
            out[B_ * NPAIR + 2 * p + 1] = (float)(j + 1);
        }
    }
}

// ---------------- init: smoothed positional table f [17 x 64] ----------------
__global__ void init_f_kernel(const float* __restrict__ pos_emb) {
    int idx = blockIdx.x * blockDim.x + threadIdx.x;
    if (idx >= NREL * PE) return;
    int r = idx / PE;
    int e = idx % PE;
    float s = 0.f;
    #pragma unroll
    for (int d = 0; d < NREL; d++) {
        int ad = d - KW; if (ad < 0) ad = -ad;
        float cnt = (float)(L_ - ad);
        int dd = r - d;
        float w = cnt * expf(-(float)(dd * dd));
        s += w * pos_emb[d * PE + e];
    }
    g_f[idx] = s;
}

// ---------------- init: A_pos (includes b1) ----------------------------------
__global__ void init_apos_kernel(const float* __restrict__ W1,
                                 const float* __restrict__ b1) {
    int idx = blockIdx.x * blockDim.x + threadIdx.x;
    if (idx >= NREL * PF) return;
    int r = idx / PF;
    int g = idx % PF;
    float s = b1[g];
    const float* w = W1 + g * PF + 2 * GCN;
    const float* f = g_f + r * PE;
    #pragma unroll 8
    for (int e = 0; e < PE; e++) s += f[e] * w[e];
    g_Apos[idx] = s;
}

// ---------------- convert: X -> A' (hi|hi|lo) bf16 ---------------------------
__global__ void conv_x_kernel(const float* __restrict__ Xe,
                              const float* __restrict__ Xc) {
    int idx = blockIdx.x * blockDim.x + threadIdx.x;
    if (idx >= M_ * GCN) return;
    int m = idx / GCN, k = idx % GCN;
    {
        float x = Xe[idx];
        __nv_bfloat16 hi = __float2bfloat16(x);
        __nv_bfloat16 lo = __float2bfloat16(x - __bfloat162float(hi));
        g_Ae[m * KP + k] = hi;
        g_Ae[m * KP + GCN + k] = hi;
        g_Ae[m * KP + 2 * GCN + k] = lo;
    }
    {
        float x = Xc[idx];
        __nv_bfloat16 hi = __float2bfloat16(x);
        __nv_bfloat16 lo = __float2bfloat16(x - __bfloat162float(hi));
        g_Ac[m * KP + k] = hi;
        g_Ac[m * KP + GCN + k] = hi;
        g_Ac[m * KP + 2 * GCN + k] = lo;
    }
}

// ---------------- convert: W1 -> B' (hi|lo|hi) bf16 --------------------------
__global__ void conv_w_kernel(const float* __restrict__ W1) {
    int idx = blockIdx.x * blockDim.x + threadIdx.x;
    if (idx >= PF * GCN) return;
    int g = idx / GCN, k = idx % GCN;
    {
        float w = W1[g * PF + k];                  // emo cols 0..511
        __nv_bfloat16 hi = __float2bfloat16(w);
        __nv_bfloat16 lo = __float2bfloat16(w - __bfloat162float(hi));
        g_Be[g * KP + k] = hi;
        g_Be[g * KP + GCN + k] = lo;
        g_Be[g * KP + 2 * GCN + k] = hi;
    }
    {
        float w = W1[g * PF + GCN + k];            // cau cols 512..1023
        __nv_bfloat16 hi = __float2bfloat16(w);
        __nv_bfloat16 lo = __float2bfloat16(w - __bfloat162float(hi));
        g_Bc[g * KP + k] = hi;
        g_Bc[g * KP + GCN + k] = lo;
        g_Bc[g * KP + 2 * GCN + k] = hi;
    }
}

// ---------------- bf16 tensor-core GEMM --------------------------------------
// C[m,g] = sum_k A'[m,k] * B'[g,k]   M=2048 N=1088 K=1536, fp32 accumulate
#define BM 128
#define BN 64
#define BK 32
#define SSTR 40          // smem row stride (bf16 elems); conflict-free
#define NSTAGE 3
#define NT (KP / BK)     // 48

__device__ __forceinline__ void cp16(void* smem, const void* g) {
    unsigned s = (unsigned)__cvta_generic_to_shared(smem);
    asm volatile("cp.async.cg.shared.global [%0], [%1], 16;\n" :: "r"(s), "l"(g));
}
#define CP_COMMIT() asm volatile("cp.async.commit_group;\n" ::: "memory")
#define CP_WAIT1()  asm volatile("cp.async.wait_group 1;\n" ::: "memory")

__global__ void __launch_bounds__(256, 2)
mma_gemm_kernel() {
    __shared__ __align__(16) __nv_bfloat16 sA[NSTAGE][BM * SSTR];
    __shared__ __align__(16) __nv_bfloat16 sB[NSTAGE][BN * SSTR];

    const int z = blockIdx.z;
    const __nv_bfloat16* __restrict__ A  = z ? g_Ac : g_Ae;
    const __nv_bfloat16* __restrict__ Bw = z ? g_Bc : g_Be;
    float* __restrict__ C = z ? g_Acau : g_Aemo;

    const int tid  = threadIdx.x;
    const int lane = tid & 31;
    const int wid  = tid >> 5;
    const int wm = wid & 3;          // 0..3 -> m offset 32*wm
    const int wn = wid >> 2;         // 0..1 -> n offset 32*wn
    const int m0 = blockIdx.y * BM;
    const int n0 = blockIdx.x * BN;

    float acc[2][4][4];
    #pragma unroll
    for (int mt = 0; mt < 2; mt++)
        #pragma unroll
        for (int nt = 0; nt < 4; nt++)
            #pragma unroll
            for (int e = 0; e < 4; e++) acc[mt][nt][e] = 0.f;

    // ---- async stage loader ----
    auto load_stage = [&](int kt, int s) {
        #pragma unroll
        for (int l = 0; l < 2; l++) {
            int q = tid + l * 256;           // 0..511
            int row = q >> 2, c8 = q & 3;    // 128 rows x 4 chunks
            cp16(&sA[s][row * SSTR + c8 * 8],
                 A + (size_t)(m0 + row) * KP + kt * BK + c8 * 8);
        }
        {
            int row = tid >> 2, c8 = tid & 3; // 64 rows x 4 chunks
            cp16(&sB[s][row * SSTR + c8 * 8],
                 Bw + (size_t)(n0 + row) * KP + kt * BK + c8 * 8);
        }
    };

    #pragma unroll
    for (int s = 0; s < NSTAGE - 1; s++) { load_stage(s, s); CP_COMMIT(); }

    for (int kt = 0; kt < NT; kt++) {
        CP_WAIT1();
        __syncthreads();
        if (kt + NSTAGE - 1 < NT) load_stage(kt + NSTAGE - 1, (kt + NSTAGE - 1) % NSTAGE);
        CP_COMMIT();

        const int s = kt % NSTAGE;
        #pragma unroll
        for (int kk = 0; kk < BK; kk += 16) {
            unsigned a[2][4], b[4][2];
            #pragma unroll
            for (int mt = 0; mt < 2; mt++) {
                const __nv_bfloat16* base =
                    &sA[s][(wm * 32 + mt * 16 + (lane >> 2)) * SSTR + kk + (lane & 3) * 2];
                a[mt][0] = *(const unsigned*)(base);
                a[mt][1] = *(const unsigned*)(base + 8 * SSTR);
                a[mt][2] = *(const unsigned*)(base + 8);
                a[mt][3] = *(const unsigned*)(base + 8 * SSTR + 8);
            }
            #pragma unroll
            for (int nt = 0; nt < 4; nt++) {
                const __nv_bfloat16* base =
                    &sB[s][(wn * 32 + nt * 8 + (lane >> 2)) * SSTR + kk + (lane & 3) * 2];
                b[nt][0] = *(const unsigned*)(base);
                b[nt][1] = *(const unsigned*)(base + 8);
            }
            #pragma unroll
            for (int mt = 0; mt < 2; mt++)
                #pragma unroll
                for (int nt = 0; nt < 4; nt++) {
                    asm volatile(
                        "mma.sync.aligned.m16n8k16.row.col.f32.bf16.bf16.f32 "
                        "{%0,%1,%2,%3}, {%4,%5,%6,%7}, {%8,%9}, {%0,%1,%2,%3};\n"
                        : "+f"(acc[mt][nt][0]), "+f"(acc[mt][nt][1]),
                          "+f"(acc[mt][nt][2]), "+f"(acc[mt][nt][3])
                        : "r"(a[mt][0]), "r"(a[mt][1]), "r"(a[mt][2]), "r"(a[mt][3]),
                          "r"(b[nt][0]), "r"(b[nt][1]));
                }
        }
    }

    // ---- store ----
    #pragma unroll
    for (int mt = 0; mt < 2; mt++) {
        int row = m0 + wm * 32 + mt * 16 + (lane >> 2);
        #pragma unroll
        for (int nt = 0; nt < 4; nt++) {
            int col = n0 + wn * 32 + nt * 8 + (lane & 3) * 2;
            *(float2*)&C[(size_t)row * PF + col] =
                make_float2(acc[mt][nt][0], acc[mt][nt][1]);
            *(float2*)&C[(size_t)(row + 8) * PF + col] =
                make_float2(acc[mt][nt][2], acc[mt][nt][3]);
        }
    }
}

// ---------------- epilogue ----------------------------------------------------
__global__ void __launch_bounds__(256)
epilogue_kernel(const float* __restrict__ W2, const float* __restrict__ b2,
                float* __restrict__ out) {
    int gw = (blockIdx.x * blockDim.x + threadIdx.x) >> 5;
    int lane = threadIdx.x & 31;
    if (gw >= B_ * NPAIR) return;
    int b = gw / NPAIR;
    int p = gw - b * NPAIR;

    int i = g_pi[p];
    int j = g_pj[p];
    int r = g_pr[p];

    const float4* ae = (const float4*)(g_Aemo + (size_t)(b * L_ + i) * PF);
    const float4* ac = (const float4*)(g_Acau + (size_t)(b * L_ + j) * PF);
    const float4* ap = (const float4*)(g_Apos + (size_t)r * PF);
    const float4* w2 = (const float4*)W2;

    float sum = 0.f;
    #pragma unroll
    for (int t = 0; t < 9; t++) {
        int c4 = t * 32 + lane;
        if (c4 < PF / 4) {
            float4 e = ae[c4];
            float4 c = ac[c4];
            float4 q = ap[c4];
            float4 w = w2[c4];
            float v0 = fmaxf(e.x + c.x + q.x, 0.f);
            float v1 = fmaxf(e.y + c.y + q.y, 0.f);
            float v2 = fmaxf(e.z + c.z + q.z, 0.f);
            float v3 = fmaxf(e.w + c.w + q.w, 0.f);
            sum = fmaf(v0, w.x, sum);
            sum = fmaf(v1, w.y, sum);
            sum = fmaf(v2, w.z, sum);
            sum = fmaf(v3, w.w, sum);
        }
    }
    #pragma unroll
    for (int o = 16; o > 0; o >>= 1)
        sum += __shfl_xor_sync(0xFFFFFFFF, sum, o);

    if (lane == 0) out[b * NPAIR + p] = sum + b2[0];
}

// ---------------- launch ------------------------------------------------------
extern "C" void kernel_launch(void* const* d_in, const int* in_sizes, int n_in,
                              void* d_out, int out_size) {
    const float* h_emo  = (const float*)d_in[0];
    const float* h_cau  = (const float*)d_in[1];
    const float* pos    = (const float*)d_in[2];
    const float* W1     = (const float*)d_in[3];
    const float* b1     = (const float*)d_in[4];
    const float* W2     = (const float*)d_in[5];
    const float* b2     = (const float*)d_in[6];
    float* out = (float*)d_out;

    init_pairs_kernel<<<1, 128>>>(out, out_size);
    init_f_kernel<<<(NREL * PE + 255) / 256, 256>>>(pos);
    init_apos_kernel<<<(NREL * PF + 255) / 256, 256>>>(W1, b1);
    conv_x_kernel<<<(M_ * GCN + 255) / 256, 256>>>(h_emo, h_cau);
    conv_w_kernel<<<(PF * GCN + 255) / 256, 256>>>(W1);

    dim3 ggrid(PF / BN, M_ / BM, 2);   // (17, 16, 2)
    mma_gemm_kernel<<<ggrid, 256>>>();

    int warps = B_ * NPAIR;
    int blocks = (warps * 32 + 255) / 256;
    epilogue_kernel<<<blocks, 256>>>(W2, b2, out);
}

// round 3
// speedup vs baseline: 1.5653x; 1.1987x over previous
#include <cuda_runtime.h>
#include <cuda_bf16.h>
#include <math.h>

// Problem constants
#define B_   16
#define L_   128
#define KW   8
#define NPAIR 2104
#define GCN  512
#define PE   64
#define PF   1088
#define PFP  1152         // PF padded to BN multiple
#define M_   2048
#define NREL 17
#define NT   48           // k-tiles: 3 segments x 16 tiles of 32

// ---------------- scratch ----------------------------------------------------
__device__ float g_Aemo[M_ * PF];
__device__ float g_Acau[M_ * PF];
__device__ float g_Apos[NREL * PF];
__device__ float g_f[NREL * PE];
__device__ int   g_pi[NPAIR];
__device__ int   g_pj[NPAIR];
__device__ int   g_pr[NPAIR];
__device__ __nv_bfloat16 g_Ahi[2][M_ * GCN];
__device__ __nv_bfloat16 g_Alo[2][M_ * GCN];
__device__ __nv_bfloat16 g_Bhi[2][PFP * GCN];
__device__ __nv_bfloat16 g_Blo[2][PFP * GCN];

// ---------------- init: pair indices -----------------------------------------
__global__ void init_pairs_kernel(float* __restrict__ out, int out_size) {
    int i = threadIdx.x;
    if (i >= L_) return;
    int off = 0;
    for (int t = 0; t < i; t++) {
        int lo = t - KW; if (lo < 0) lo = 0;
        int hi = t + KW; if (hi > L_ - 1) hi = L_ - 1;
        off += hi - lo + 1;
    }
    int lo = i - KW; if (lo < 0) lo = 0;
    int hi = i + KW; if (hi > L_ - 1) hi = L_ - 1;
    bool write_pos = (out_size == B_ * NPAIR + 2 * NPAIR);
    for (int j = lo; j <= hi; j++) {
        int p = off + (j - lo);
        g_pi[p] = i;
        g_pj[p] = j;
        g_pr[p] = (j - i) + KW;
        if (write_pos) {
            out[B_ * NPAIR + 2 * p + 0] = (float)(i + 1);
            out[B_ * NPAIR + 2 * p + 1] = (float)(j + 1);
        }
    }
}

// ---------------- init: smoothed positional table f [17 x 64] ----------------
__global__ void init_f_kernel(const float* __restrict__ pos_emb) {
    int idx = blockIdx.x * blockDim.x + threadIdx.x;
    if (idx >= NREL * PE) return;
    int r = idx / PE;
    int e = idx % PE;
    float s = 0.f;
    #pragma unroll
    for (int d = 0; d < NREL; d++) {
        int ad = d - KW; if (ad < 0) ad = -ad;
        float cnt = (float)(L_ - ad);
        int dd = r - d;
        float w = cnt * expf(-(float)(dd * dd));
        s += w * pos_emb[d * PE + e];
    }
    g_f[idx] = s;
}

// ---------------- init: A_pos (includes b1) ----------------------------------
__global__ void init_apos_kernel(const float* __restrict__ W1,
                                 const float* __restrict__ b1) {
    int idx = blockIdx.x * blockDim.x + threadIdx.x;
    if (idx >= NREL * PF) return;
    int r = idx / PF;
    int g = idx % PF;
    float s = b1[g];
    const float* w = W1 + g * PF + 2 * GCN;
    const float* f = g_f + r * PE;
    #pragma unroll 8
    for (int e = 0; e < PE; e++) s += f[e] * w[e];
    g_Apos[idx] = s;
}

// ---------------- convert: X -> hi/lo bf16 ------------------------------------
__global__ void conv_x_kernel(const float* __restrict__ Xe,
                              const float* __restrict__ Xc) {
    int idx = blockIdx.x * blockDim.x + threadIdx.x;
    if (idx >= M_ * GCN) return;
    {
        float x = Xe[idx];
        __nv_bfloat16 hi = __float2bfloat16(x);
        g_Ahi[0][idx] = hi;
        g_Alo[0][idx] = __float2bfloat16(x - __bfloat162float(hi));
    }
    {
        float x = Xc[idx];
        __nv_bfloat16 hi = __float2bfloat16(x);
        g_Ahi[1][idx] = hi;
        g_Alo[1][idx] = __float2bfloat16(x - __bfloat162float(hi));
    }
}

// ---------------- convert: W1 -> hi/lo bf16 -----------------------------------
__global__ void conv_w_kernel(const float* __restrict__ W1) {
    int idx = blockIdx.x * blockDim.x + threadIdx.x;
    if (idx >= PF * GCN) return;
    int g = idx / GCN, k = idx % GCN;
    {
        float w = W1[g * PF + k];
        __nv_bfloat16 hi = __float2bfloat16(w);
        g_Bhi[0][g * GCN + k] = hi;
        g_Blo[0][g * GCN + k] = __float2bfloat16(w - __bfloat162float(hi));
    }
    {
        float w = W1[g * PF + GCN + k];
        __nv_bfloat16 hi = __float2bfloat16(w);
        g_Bhi[1][g * GCN + k] = hi;
        g_Blo[1][g * GCN + k] = __float2bfloat16(w - __bfloat162float(hi));
    }
}

// ---------------- bf16 tensor-core GEMM (128x128x32, ldmatrix, 3-stage) ------
#define BM 128
#define BN 128
#define BK 32
#define SSTR 40
#define NSTAGE 3
#define SA_ELEMS (BM * SSTR)
#define SB_ELEMS (BN * SSTR)
#define STAGE_ELEMS (SA_ELEMS + SB_ELEMS)

__device__ __forceinline__ void cp16(void* smem, const void* g) {
    unsigned s = (unsigned)__cvta_generic_to_shared(smem);
    asm volatile("cp.async.cg.shared.global [%0], [%1], 16;\n" :: "r"(s), "l"(g));
}
#define CP_COMMIT() asm volatile("cp.async.commit_group;\n" ::: "memory")
#define CP_WAIT1()  asm volatile("cp.async.wait_group 1;\n" ::: "memory")

__device__ __forceinline__ void ldsm4(unsigned& r0, unsigned& r1,
                                      unsigned& r2, unsigned& r3,
                                      const __nv_bfloat16* p) {
    unsigned a = (unsigned)__cvta_generic_to_shared(p);
    asm volatile("ldmatrix.sync.aligned.m8n8.x4.shared.b16 {%0,%1,%2,%3}, [%4];\n"
                 : "=r"(r0), "=r"(r1), "=r"(r2), "=r"(r3) : "r"(a));
}

extern __shared__ __align__(16) __nv_bfloat16 dynsmem[];

__global__ void __launch_bounds__(256, 2)
mma_gemm_kernel() {
    const int z = blockIdx.z;
    const __nv_bfloat16* __restrict__ Ahi = g_Ahi[z];
    const __nv_bfloat16* __restrict__ Alo = g_Alo[z];
    const __nv_bfloat16* __restrict__ Bhi = g_Bhi[z];
    const __nv_bfloat16* __restrict__ Blo = g_Blo[z];
    float* __restrict__ C = z ? g_Acau : g_Aemo;

    const int tid  = threadIdx.x;
    const int lane = tid & 31;
    const int wid  = tid >> 5;
    const int wmBase = (wid & 1) * 64;     // 2 warp-rows of 64
    const int wnBase = (wid >> 1) * 32;    // 4 warp-cols of 32
    const int m0 = blockIdx.y * BM;
    const int n0 = blockIdx.x * BN;

    // ldmatrix per-lane sub-addresses
    const int aRow = (lane & 7) + ((lane >> 3) & 1) * 8;
    const int aK   = (lane >> 4) * 8;
    const int bRow = (lane & 7) + (lane >> 4) * 8;
    const int bK   = ((lane >> 3) & 1) * 8;

    float acc[4][4][4];
    #pragma unroll
    for (int mt = 0; mt < 4; mt++)
        #pragma unroll
        for (int nt = 0; nt < 4; nt++)
            #pragma unroll
            for (int e = 0; e < 4; e++) acc[mt][nt][e] = 0.f;

    auto load_stage = [&](int kt, int s) {
        const int seg = kt >> 4;
        const int kc  = (kt & 15) * BK;
        const __nv_bfloat16* __restrict__ Asrc = (seg < 2) ? Ahi : Alo;
        const __nv_bfloat16* __restrict__ Bsrc = (seg == 1) ? Blo : Bhi;
        __nv_bfloat16* sA = dynsmem + s * STAGE_ELEMS;
        __nv_bfloat16* sB = sA + SA_ELEMS;
        #pragma unroll
        for (int l = 0; l < 2; l++) {
            int q = tid + l * 256;
            int row = q >> 2, c8 = (q & 3) * 8;
            cp16(&sA[row * SSTR + c8],
                 Asrc + (size_t)(m0 + row) * GCN + kc + c8);
        }
        #pragma unroll
        for (int l = 0; l < 2; l++) {
            int q = tid + l * 256;
            int row = q >> 2, c8 = (q & 3) * 8;
            cp16(&sB[row * SSTR + c8],
                 Bsrc + (size_t)(n0 + row) * GCN + kc + c8);
        }
    };

    load_stage(0, 0); CP_COMMIT();
    load_stage(1, 1); CP_COMMIT();

    for (int kt = 0; kt < NT; kt++) {
        CP_WAIT1();
        __syncthreads();
        if (kt + 2 < NT) load_stage(kt + 2, (kt + 2) % NSTAGE);
        CP_COMMIT();

        const int s = kt % NSTAGE;
        const __nv_bfloat16* sA = dynsmem + s * STAGE_ELEMS;
        const __nv_bfloat16* sB = sA + SA_ELEMS;

        #pragma unroll
        for (int kk = 0; kk < BK; kk += 16) {
            unsigned a[4][4], b[2][4];
            #pragma unroll
            for (int mt = 0; mt < 4; mt++)
                ldsm4(a[mt][0], a[mt][1], a[mt][2], a[mt][3],
                      &sA[(wmBase + mt * 16 + aRow) * SSTR + kk + aK]);
            #pragma unroll
            for (int ntp = 0; ntp < 2; ntp++)
                ldsm4(b[ntp][0], b[ntp][1], b[ntp][2], b[ntp][3],
                      &sB[(wnBase + ntp * 16 + bRow) * SSTR + kk + bK]);
            #pragma unroll
            for (int mt = 0; mt < 4; mt++)
                #pragma unroll
                for (int nt = 0; nt < 4; nt++) {
                    unsigned b0 = b[nt >> 1][(nt & 1) * 2];
                    unsigned b1 = b[nt >> 1][(nt & 1) * 2 + 1];
                    asm volatile(
                        "mma.sync.aligned.m16n8k16.row.col.f32.bf16.bf16.f32 "
                        "{%0,%1,%2,%3}, {%4,%5,%6,%7}, {%8,%9}, {%0,%1,%2,%3};\n"
                        : "+f"(acc[mt][nt][0]), "+f"(acc[mt][nt][1]),
                          "+f"(acc[mt][nt][2]), "+f"(acc[mt][nt][3])
                        : "r"(a[mt][0]), "r"(a[mt][1]), "r"(a[mt][2]), "r"(a[mt][3]),
                          "r"(b0), "r"(b1));
                }
        }
    }

    // ---- store (guard columns >= PF from padded tile) ----
    #pragma unroll
    for (int mt = 0; mt < 4; mt++) {
        int row = m0 + wmBase + mt * 16 + (lane >> 2);
        #pragma unroll
        for (int nt = 0; nt < 4; nt++) {
            int col = n0 + wnBase + nt * 8 + (lane & 3) * 2;
            if (col < PF) {
                *(float2*)&C[(size_t)row * PF + col] =
                    make_float2(acc[mt][nt][0], acc[mt][nt][1]);
                *(float2*)&C[(size_t)(row + 8) * PF + col] =
                    make_float2(acc[mt][nt][2], acc[mt][nt][3]);
            }
        }
    }
}

// ---------------- epilogue ----------------------------------------------------
__global__ void __launch_bounds__(256)
epilogue_kernel(const float* __restrict__ W2, const float* __restrict__ b2,
                float* __restrict__ out) {
    int gw = (blockIdx.x * blockDim.x + threadIdx.x) >> 5;
    int lane = threadIdx.x & 31;
    if (gw >= B_ * NPAIR) return;
    int b = gw / NPAIR;
    int p = gw - b * NPAIR;

    int i = g_pi[p];
    int j = g_pj[p];
    int r = g_pr[p];

    const float4* ae = (const float4*)(g_Aemo + (size_t)(b * L_ + i) * PF);
    const float4* ac = (const float4*)(g_Acau + (size_t)(b * L_ + j) * PF);
    const float4* ap = (const float4*)(g_Apos + (size_t)r * PF);
    const float4* w2 = (const float4*)W2;

    float sum = 0.f;
    #pragma unroll
    for (int t = 0; t < 9; t++) {
        int c4 = t * 32 + lane;
        if (c4 < PF / 4) {
            float4 e = ae[c4];
            float4 c = ac[c4];
            float4 q = ap[c4];
            float4 w = w2[c4];
            float v0 = fmaxf(e.x + c.x + q.x, 0.f);
            float v1 = fmaxf(e.y + c.y + q.y, 0.f);
            float v2 = fmaxf(e.z + c.z + q.z, 0.f);
            float v3 = fmaxf(e.w + c.w + q.w, 0.f);
            sum = fmaf(v0, w.x, sum);
            sum = fmaf(v1, w.y, sum);
            sum = fmaf(v2, w.z, sum);
            sum = fmaf(v3, w.w, sum);
        }
    }
    #pragma unroll
    for (int o = 16; o > 0; o >>= 1)
        sum += __shfl_xor_sync(0xFFFFFFFF, sum, o);

    if (lane == 0) out[b * NPAIR + p] = sum + b2[0];
}

// ---------------- launch ------------------------------------------------------
extern "C" void kernel_launch(void* const* d_in, const int* in_sizes, int n_in,
                              void* d_out, int out_size) {
    const float* h_emo  = (const float*)d_in[0];
    const float* h_cau  = (const float*)d_in[1];
    const float* pos    = (const float*)d_in[2];
    const float* W1     = (const float*)d_in[3];
    const float* b1     = (const float*)d_in[4];
    const float* W2     = (const float*)d_in[5];
    const float* b2     = (const float*)d_in[6];
    float* out = (float*)d_out;

    static int smem_bytes = NSTAGE * STAGE_ELEMS * (int)sizeof(__nv_bfloat16);
    cudaFuncSetAttribute(mma_gemm_kernel,
                         cudaFuncAttributeMaxDynamicSharedMemorySize, smem_bytes);

    init_pairs_kernel<<<1, 128>>>(out, out_size);
    init_f_kernel<<<(NREL * PE + 255) / 256, 256>>>(pos);
    init_apos_kernel<<<(NREL * PF + 255) / 256, 256>>>(W1, b1);
    conv_x_kernel<<<(M_ * GCN + 255) / 256, 256>>>(h_emo, h_cau);
    conv_w_kernel<<<(PF * GCN + 255) / 256, 256>>>(W1);

    dim3 ggrid(PFP / BN, M_ / BM, 2);   // (9, 16, 2) = 288 blocks: one wave
    mma_gemm_kernel<<<ggrid, 256, smem_bytes>>>();

    int warps = B_ * NPAIR;
    int blocks = (warps * 32 + 255) / 256;
    epilogue_kernel<<<blocks, 256>>>(W2, b2, out);
}